// round 10
// baseline (speedup 1.0000x reference)
#include <cuda_runtime.h>
#include <cuda_fp16.h>
#include <cstdint>

// ---------------------------------------------------------------------------
// Plane_refine on sm_100: 2-layer pointwise MLP via fp16 mma.sync (f32 accum)
// + masked max-pool. 296 CTAs x 256 thr (2/SM), 64-pt tiles, m32n32 warp grid.
// Cross-tile software pipeline: next tile's feature is prefetched into
// registers during layer-2/epilogue/pool, so the loop-top is STS-only.
// H1 f16 round-trip; H2 f16 aliases A; warp-private masks. 4 barriers/tile.
// ---------------------------------------------------------------------------

constexpr int N_PTS   = 131072;
constexpr int TILE    = 64;
constexpr int NT      = N_PTS / TILE;     // 2048
constexpr int GRID    = 296;              // 2 per SM
constexpr int THREADS = 256;
constexpr int P       = 64;

// smem. f16 rows: 128 f16 = 256 B, 16B-chunk XOR swizzle chunk' = chunk^(row&7).
constexpr int OFF_W1  = 0;          // 32 KB
constexpr int OFF_W2  = 32768;      // 32 KB
constexpr int OFF_A   = 65536;      // 16 KB (64 rows): feature f16, later H2 f16
constexpr int OFF_H1  = 81920;      // 16 KB (64 rows): H1 f16
constexpr int OFF_MISC = 98304;
constexpr int OFF_B1   = OFF_MISC + 0;      // f32[128]
constexpr int OFF_B2   = OFF_MISC + 512;    // f32[128]
constexpr int OFF_PL   = OFF_MISC + 1024;   // f32[640]
constexpr int OFF_CTR  = OFF_MISC + 3584;   // f32[4]
constexpr int OFF_PMS  = OFF_MISC + 3600;   // u32[64][2]
constexpr int SMEM_BYTES = OFF_MISC + 4640; // ~103 KB -> 2 CTAs/SM

__device__ __forceinline__ uint32_t smem_u32(const void* p) {
    uint32_t a;
    asm("{ .reg .u64 t; cvta.to.shared.u64 t, %1; cvt.u32.u64 %0, t; }"
        : "=r"(a) : "l"(p));
    return a;
}

__device__ __forceinline__ uint32_t swz(uint32_t region, int row, int kc) {
    return region + (uint32_t)(row * 256) + (uint32_t)((kc ^ (row & 7)) << 4);
}

__device__ __forceinline__ uint32_t pack_h2(float a, float b) {
    __half2 h = __floats2half2_rn(a, b);
    return *(uint32_t*)&h;
}

#define LDSM_X4(r0, r1, r2, r3, a) \
    asm volatile("ldmatrix.sync.aligned.m8n8.x4.shared.b16 {%0,%1,%2,%3}, [%4];" \
                 : "=r"(r0), "=r"(r1), "=r"(r2), "=r"(r3) : "r"(a))
#define MMA16816(d, a0, a1, a2, a3, b0, b1) \
    asm volatile("mma.sync.aligned.m16n8k16.row.col.f32.f16.f16.f32 " \
                 "{%0,%1,%2,%3}, {%4,%5,%6,%7}, {%8,%9}, {%0,%1,%2,%3};" \
                 : "+f"((d)[0]), "+f"((d)[1]), "+f"((d)[2]), "+f"((d)[3]) \
                 : "r"(a0), "r"(a1), "r"(a2), "r"(a3), "r"(b0), "r"(b1))

// One 64x128x128 layer for this warp's 32x32 block (R7-verified fragment math).
__device__ __forceinline__ void do_layer(uint32_t aB, uint32_t wB,
                                         float acc[2][4][4],
                                         int r2, int c2, int lane)
{
    const int arow  = 32 * r2 + (lane & 15);
    const int abit  = (lane >> 4) & 1;
    const int rs    = arow & 7;
    const uint32_t aoff = (uint32_t)(arow * 256);
    const int bn    = 32 * c2 + (lane & 7) + (((lane >> 4) & 1) << 3);
    const int bbit  = (lane >> 3) & 1;
    const int ns    = bn & 7;
    const uint32_t boff = (uint32_t)(bn * 256);

#pragma unroll
    for (int kk = 0; kk < 8; kk++) {
        const uint32_t kcA = (uint32_t)(((2 * kk + abit) ^ rs) << 4);
        const uint32_t kcB = (uint32_t)(((2 * kk + bbit) ^ ns) << 4);
        uint32_t a[8], b[8];
        LDSM_X4(a[0], a[1], a[2], a[3], aB + aoff + kcA);
        LDSM_X4(a[4], a[5], a[6], a[7], aB + aoff + 4096 + kcA);
        LDSM_X4(b[0], b[1], b[2], b[3], wB + boff + kcB);
        LDSM_X4(b[4], b[5], b[6], b[7], wB + boff + 4096 + kcB);
#pragma unroll
        for (int i = 0; i < 2; i++) {
            const uint32_t* A = &a[4 * i];
#pragma unroll
            for (int j = 0; j < 4; j++)
                MMA16816(acc[i][j], A[0], A[1], A[2], A[3], b[2 * j], b[2 * j + 1]);
        }
    }
}

__global__ void __launch_bounds__(THREADS, 2)
plane_refine_pf(const float* __restrict__ feature, const float* __restrict__ xyz,
                const float* __restrict__ centers,
                const float* __restrict__ plane_center, const float* __restrict__ plane_normal,
                const float* __restrict__ plane_min, const float* __restrict__ plane_max,
                const float* __restrict__ W1, const float* __restrict__ g1,
                const float* __restrict__ b1,
                const float* __restrict__ W2, const float* __restrict__ g2,
                const float* __restrict__ b2,
                float* __restrict__ out)
{
    extern __shared__ char smem[];
    const uint32_t sb = smem_u32(smem);

    float*    b1s = (float*)(smem + OFF_B1);
    float*    b2s = (float*)(smem + OFF_B2);
    float*    pl  = (float*)(smem + OFF_PL);
    float*    ctr = (float*)(smem + OFF_CTR);
    unsigned* pms = (unsigned*)(smem + OFF_PMS);

    const int tid  = threadIdx.x;
    const int lane = tid & 31;
    const int wg   = tid >> 5;      // 0..7
    const int r2   = wg & 1;        // m-block (rows 32*r2..)
    const int c2   = wg >> 1;       // n-block (cols 32*c2..)
    const int g    = lane >> 2;
    const int tig  = lane & 3;

    // ---- prologue: weights (fold g, f16, swizzled), consts
    for (int idx = tid; idx < 16384; idx += THREADS) {
        const int o = idx >> 7, k = idx & 127;
        const uint32_t a1 = swz(0, o, k >> 3) + (uint32_t)((k & 7) * 2);
        *(__half*)(smem + a1 + OFF_W1) = __float2half_rn(W1[idx] * g1[o]);
        *(__half*)(smem + a1 + OFF_W2) = __float2half_rn(W2[idx] * g2[o]);
    }
    if (tid < 128) { b1s[tid] = b1[tid]; b2s[tid] = b2[tid]; }
    if (tid < P) {
        const float nx = plane_normal[tid * 3 + 0];
        const float ny = plane_normal[tid * 3 + 1];
        const float nz = plane_normal[tid * 3 + 2];
        pl[tid]       = nx;  pl[64 + tid]  = ny;  pl[128 + tid] = nz;
        pl[192 + tid] = plane_center[tid * 3 + 0] * nx
                      + plane_center[tid * 3 + 1] * ny
                      + plane_center[tid * 3 + 2] * nz;
        pl[256 + tid] = plane_min[tid * 3 + 0];
        pl[320 + tid] = plane_min[tid * 3 + 1];
        pl[384 + tid] = plane_min[tid * 3 + 2];
        pl[448 + tid] = plane_max[tid * 3 + 0];
        pl[512 + tid] = plane_max[tid * 3 + 1];
        pl[576 + tid] = plane_max[tid * 3 + 2];
    }
    if (tid < 3) ctr[tid] = centers[tid];
    __syncthreads();

    const float cx = ctr[0], cy = ctr[1], cz = ctr[2];

    // warp owns planes 8*wg..8*wg+7; lane owns dims 4*lane..4*lane+3
    float4 poolv[8];
#pragma unroll
    for (int j = 0; j < 8; j++) poolv[j] = make_float4(0.f, 0.f, 0.f, 0.f);

    // ---- prefetch first tile's feature into registers
    float4 pf[8];
    {
        const float4* src = (const float4*)(feature + (size_t)blockIdx.x * TILE * 128);
#pragma unroll
        for (int jj = 0; jj < 8; jj++) pf[jj] = src[tid + jj * THREADS];
    }

    for (int t = blockIdx.x; t < NT; t += GRID) {
        const int gbase = t * TILE;

        // ---- STS-only: prefetched feature -> f16 A (swizzled)
#pragma unroll
        for (int jj = 0; jj < 8; jj++) {
            const int idx = tid + jj * THREADS;      // 2048 float4
            const int pt  = idx >> 5, k4 = idx & 31;
            const uint32_t a = swz(OFF_A, pt, k4 >> 1) + (uint32_t)((k4 & 1) * 8);
            *(uint2*)(smem + a) = make_uint2(pack_h2(pf[jj].x, pf[jj].y),
                                             pack_h2(pf[jj].z, pf[jj].w));
        }

        // ---- masks (warp-private: warp writes & reads only its 8 planes)
#pragma unroll
        for (int h = 0; h < 2; h++) {
            const int pt = gbase + 32 * h + lane;
            const float px = xyz[(size_t)pt * 3 + 0] + cx;
            const float py = xyz[(size_t)pt * 3 + 1] + cy;
            const float pz = xyz[(size_t)pt * 3 + 2] + cz;
#pragma unroll
            for (int j = 0; j < 8; j++) {
                const int p = 8 * wg + j;
                const float d = fabsf(px * pl[p] + py * pl[64 + p] + pz * pl[128 + p]
                                      - pl[192 + p]);
                bool ok = d < 0.05f;
                float mn, mx;
                mn = pl[256 + p]; mx = pl[448 + p];
                ok = ok && ((px >= mn && px < mx) || (mx == 0.f));
                mn = pl[320 + p]; mx = pl[512 + p];
                ok = ok && ((py >= mn && py < mx) || (mx == 0.f));
                mn = pl[384 + p]; mx = pl[576 + p];
                ok = ok && ((pz >= mn && pz < mx) || (mx == 0.f));
                const unsigned bal = __ballot_sync(0xffffffffu, ok);
                if (lane == 0) pms[p * 2 + h] = bal;
            }
        }
        __syncthreads();   // bar1: A ready

        // ---- layer 1 ----
        float acc[2][4][4];
#pragma unroll
        for (int i = 0; i < 2; i++)
#pragma unroll
            for (int j = 0; j < 4; j++)
#pragma unroll
                for (int q = 0; q < 4; q++) acc[i][j][q] = 0.f;

        do_layer(sb + OFF_A, sb + OFF_W1, acc, r2, c2, lane);

        // ---- epilogue 1: +b1, relu, f16 into H1
#pragma unroll
        for (int i = 0; i < 2; i++)
#pragma unroll
            for (int h = 0; h < 2; h++) {
                const int row = 32 * r2 + 16 * i + 8 * h + g;
#pragma unroll
                for (int j = 0; j < 4; j++) {
                    const int col0 = 32 * c2 + 8 * j + 2 * tig;
                    const float2 bb = *(const float2*)&b1s[col0];
                    const float v0 = fmaxf(acc[i][j][2 * h + 0] + bb.x, 0.f);
                    const float v1 = fmaxf(acc[i][j][2 * h + 1] + bb.y, 0.f);
                    const uint32_t a = swz(OFF_H1, row, 4 * c2 + j) + (uint32_t)(4 * tig);
                    *(uint32_t*)(smem + a) = pack_h2(v0, v1);
                }
            }
        __syncthreads();   // bar2: H1 ready; all A-reads done

        // ---- layer 2 ----
#pragma unroll
        for (int i = 0; i < 2; i++)
#pragma unroll
            for (int j = 0; j < 4; j++)
#pragma unroll
                for (int q = 0; q < 4; q++) acc[i][j][q] = 0.f;

        do_layer(sb + OFF_H1, sb + OFF_W2, acc, r2, c2, lane);

        // ---- prefetch next tile's feature (latency hidden under epi2+pool)
        {
            const int nt_ = t + GRID;
            if (nt_ < NT) {
                const float4* src = (const float4*)(feature + (size_t)nt_ * TILE * 128);
#pragma unroll
                for (int jj = 0; jj < 8; jj++) pf[jj] = src[tid + jj * THREADS];
            }
        }

        // ---- epilogue 2: +b2, relu, f16 into A region (H2)
#pragma unroll
        for (int i = 0; i < 2; i++)
#pragma unroll
            for (int h = 0; h < 2; h++) {
                const int row = 32 * r2 + 16 * i + 8 * h + g;
#pragma unroll
                for (int j = 0; j < 4; j++) {
                    const int col0 = 32 * c2 + 8 * j + 2 * tig;
                    const float2 bb = *(const float2*)&b2s[col0];
                    const float v0 = fmaxf(acc[i][j][2 * h + 0] + bb.x, 0.f);
                    const float v1 = fmaxf(acc[i][j][2 * h + 1] + bb.y, 0.f);
                    const uint32_t a = swz(OFF_A, row, 4 * c2 + j) + (uint32_t)(4 * tig);
                    *(uint32_t*)(smem + a) = pack_h2(v0, v1);
                }
            }
        __syncthreads();   // bar3: H2 ready

        // ---- pool: warp's 8 planes over 64 points (f16 H2, f32 max)
#pragma unroll
        for (int j = 0; j < 8; j++) {
            const int p = 8 * wg + j;
#pragma unroll
            for (int h = 0; h < 2; h++) {
                unsigned bits = pms[p * 2 + h];
                while (bits) {
                    const int i = __ffs(bits) - 1;
                    bits &= bits - 1;
                    const int pt = 32 * h + i;
                    const uint2 raw = *(const uint2*)
                        (smem + swz(OFF_A, pt, lane >> 1) + 8 * (lane & 1));
                    const float2 v0 = __half22float2(*(const __half2*)&raw.x);
                    const float2 v1 = __half22float2(*(const __half2*)&raw.y);
                    poolv[j].x = fmaxf(poolv[j].x, v0.x);
                    poolv[j].y = fmaxf(poolv[j].y, v0.y);
                    poolv[j].z = fmaxf(poolv[j].z, v1.x);
                    poolv[j].w = fmaxf(poolv[j].w, v1.y);
                }
            }
        }
        __syncthreads();   // bar4: pool done; next STS may overwrite A
    }

    // ---- merge (nonneg float max == uint max on float bits)
    {
        unsigned* o32 = (unsigned*)out;
#pragma unroll
        for (int j = 0; j < 8; j++) {
            const int p = 8 * wg + j;
            const int bidx = p * 128 + lane * 4;
            atomicMax(&o32[bidx + 0], __float_as_uint(poolv[j].x));
            atomicMax(&o32[bidx + 1], __float_as_uint(poolv[j].y));
            atomicMax(&o32[bidx + 2], __float_as_uint(poolv[j].z));
            atomicMax(&o32[bidx + 3], __float_as_uint(poolv[j].w));
        }
    }
}

__global__ void zero_out_kernel(float* __restrict__ out, int n) {
    const int i = blockIdx.x * blockDim.x + threadIdx.x;
    if (i < n) out[i] = 0.f;
}

extern "C" void kernel_launch(void* const* d_in, const int* in_sizes, int n_in,
                              void* d_out, int out_size)
{
    const float* feature      = (const float*)d_in[0];
    const float* xyz          = (const float*)d_in[1];
    const float* centers      = (const float*)d_in[2];
    const float* plane_center = (const float*)d_in[3];
    const float* plane_normal = (const float*)d_in[4];
    const float* plane_min    = (const float*)d_in[5];
    const float* plane_max    = (const float*)d_in[6];
    const float* W1           = (const float*)d_in[7];
    const float* g1           = (const float*)d_in[8];
    const float* b1           = (const float*)d_in[9];
    const float* W2           = (const float*)d_in[10];
    const float* g2           = (const float*)d_in[11];
    const float* b2           = (const float*)d_in[12];
    float* out = (float*)d_out;

    cudaFuncSetAttribute(plane_refine_pf,
                         cudaFuncAttributeMaxDynamicSharedMemorySize, SMEM_BYTES);

    zero_out_kernel<<<(P * 128 + 255) / 256, 256>>>(out, P * 128);
    plane_refine_pf<<<GRID, THREADS, SMEM_BYTES>>>(
        feature, xyz, centers, plane_center, plane_normal, plane_min, plane_max,
        W1, g1, b1, W2, g2, b2, out);
}

// round 12
// speedup vs baseline: 1.1025x; 1.1025x over previous
#include <cuda_runtime.h>
#include <cuda_fp16.h>
#include <cstdint>

// ---------------------------------------------------------------------------
// Plane_refine on sm_100: 2-layer pointwise MLP via fp16 mma.sync (f32 accum)
// + masked max-pool. 148 CTAs x 512 thr (1 CTA/SM), 256-pt tiles.
// Warp grid 8m x 2n, warp tile m32 x n64: A-replicas 2, B-replicas 8 over
// 256 pts = 1.5 KB/pt LDSM (-25% vs m32n32 over 128 pts). H1 f16 roundtrip,
// H2 f16 aliases A, pool accumulates in f16 (__hmax2, exact on f16 inputs).
// ---------------------------------------------------------------------------

constexpr int N_PTS   = 131072;
constexpr int TILE    = 256;
constexpr int NT      = N_PTS / TILE;     // 512
constexpr int GRID    = 148;
constexpr int THREADS = 512;
constexpr int P       = 64;

// smem. f16 rows: 128 f16 = 256 B, 16B-chunk XOR swizzle chunk' = chunk^(row&7).
constexpr int OFF_W1  = 0;          // 32 KB
constexpr int OFF_W2  = 32768;      // 32 KB
constexpr int OFF_A   = 65536;      // 64 KB (256 rows): feature f16, later H2 f16
constexpr int OFF_H1  = 131072;     // 64 KB (256 rows): H1 f16
constexpr int OFF_MISC = 196608;
constexpr int OFF_B1   = OFF_MISC + 0;      // f32[128]
constexpr int OFF_B2   = OFF_MISC + 512;    // f32[128]
constexpr int OFF_PL   = OFF_MISC + 1024;   // f32[640]
constexpr int OFF_CTR  = OFF_MISC + 3584;   // f32[4]
constexpr int OFF_PMS  = OFF_MISC + 3600;   // u32[64][8] = 2048 B
constexpr int SMEM_BYTES = OFF_MISC + 5664; // ~198 KB -> 1 CTA/SM

__device__ __forceinline__ uint32_t smem_u32(const void* p) {
    uint32_t a;
    asm("{ .reg .u64 t; cvta.to.shared.u64 t, %1; cvt.u32.u64 %0, t; }"
        : "=r"(a) : "l"(p));
    return a;
}

__device__ __forceinline__ uint32_t swz(uint32_t region, int row, int kc) {
    return region + (uint32_t)(row * 256) + (uint32_t)((kc ^ (row & 7)) << 4);
}

__device__ __forceinline__ uint32_t pack_h2(float a, float b) {
    __half2 h = __floats2half2_rn(a, b);
    return *(uint32_t*)&h;
}

#define LDSM_X4(r0, r1, r2, r3, a) \
    asm volatile("ldmatrix.sync.aligned.m8n8.x4.shared.b16 {%0,%1,%2,%3}, [%4];" \
                 : "=r"(r0), "=r"(r1), "=r"(r2), "=r"(r3) : "r"(a))
#define MMA16816(d, a0, a1, a2, a3, b0, b1) \
    asm volatile("mma.sync.aligned.m16n8k16.row.col.f32.f16.f16.f32 " \
                 "{%0,%1,%2,%3}, {%4,%5,%6,%7}, {%8,%9}, {%0,%1,%2,%3};" \
                 : "+f"((d)[0]), "+f"((d)[1]), "+f"((d)[2]), "+f"((d)[3]) \
                 : "r"(a0), "r"(a1), "r"(a2), "r"(a3), "r"(b0), "r"(b1))

// One m32 x n64 x k128 block (verified fragment math; B non-trans ldmatrix).
__device__ __forceinline__ void do_layer(uint32_t aB, uint32_t wB,
                                         float acc[2][8][4],
                                         int r2, int c2, int lane)
{
    const int arow  = 32 * r2 + (lane & 15);
    const int abit  = (lane >> 4) & 1;
    const int rs    = arow & 7;
    const uint32_t aoff = (uint32_t)(arow * 256);
    const int bn    = 64 * c2 + (lane & 7) + (((lane >> 4) & 1) << 3);
    const int bbit  = (lane >> 3) & 1;
    const int ns    = bn & 7;
    const uint32_t boff = (uint32_t)(bn * 256);

#pragma unroll
    for (int kk = 0; kk < 8; kk++) {
        const uint32_t kcA = (uint32_t)(((2 * kk + abit) ^ rs) << 4);
        const uint32_t kcB = (uint32_t)(((2 * kk + bbit) ^ ns) << 4);
        uint32_t a[8], b[16];
        LDSM_X4(a[0], a[1], a[2], a[3], aB + aoff + kcA);
        LDSM_X4(a[4], a[5], a[6], a[7], aB + aoff + 4096 + kcA);
#pragma unroll
        for (int nb = 0; nb < 4; nb++)
            LDSM_X4(b[4 * nb], b[4 * nb + 1], b[4 * nb + 2], b[4 * nb + 3],
                    wB + boff + (uint32_t)(nb * 4096) + kcB);
#pragma unroll
        for (int i = 0; i < 2; i++) {
            const uint32_t* A = &a[4 * i];
#pragma unroll
            for (int j = 0; j < 8; j++)
                MMA16816(acc[i][j], A[0], A[1], A[2], A[3], b[2 * j], b[2 * j + 1]);
        }
    }
}

__global__ void __launch_bounds__(THREADS, 1)
plane_refine_w64(const float* __restrict__ feature, const float* __restrict__ xyz,
                 const float* __restrict__ centers,
                 const float* __restrict__ plane_center, const float* __restrict__ plane_normal,
                 const float* __restrict__ plane_min, const float* __restrict__ plane_max,
                 const float* __restrict__ W1, const float* __restrict__ g1,
                 const float* __restrict__ b1,
                 const float* __restrict__ W2, const float* __restrict__ g2,
                 const float* __restrict__ b2,
                 float* __restrict__ out)
{
    extern __shared__ char smem[];
    const uint32_t sb = smem_u32(smem);

    float*    b1s = (float*)(smem + OFF_B1);
    float*    b2s = (float*)(smem + OFF_B2);
    float*    pl  = (float*)(smem + OFF_PL);
    float*    ctr = (float*)(smem + OFF_CTR);
    unsigned* pms = (unsigned*)(smem + OFF_PMS);

    const int tid  = threadIdx.x;
    const int lane = tid & 31;
    const int wg   = tid >> 5;      // 0..15
    const int r2   = wg & 7;        // m-block: rows 32*r2
    const int c2   = wg >> 3;       // n-block: cols 64*c2
    const int g    = lane >> 2;
    const int tig  = lane & 3;

    // ---- prologue: weights (fold g, f16, swizzled), consts
    for (int idx = tid; idx < 16384; idx += THREADS) {
        const int o = idx >> 7, k = idx & 127;
        const uint32_t a1 = swz(0, o, k >> 3) + (uint32_t)((k & 7) * 2);
        *(__half*)(smem + a1 + OFF_W1) = __float2half_rn(W1[idx] * g1[o]);
        *(__half*)(smem + a1 + OFF_W2) = __float2half_rn(W2[idx] * g2[o]);
    }
    if (tid < 128) { b1s[tid] = b1[tid]; b2s[tid] = b2[tid]; }
    if (tid < P) {
        const float nx = plane_normal[tid * 3 + 0];
        const float ny = plane_normal[tid * 3 + 1];
        const float nz = plane_normal[tid * 3 + 2];
        pl[tid]       = nx;  pl[64 + tid]  = ny;  pl[128 + tid] = nz;
        pl[192 + tid] = plane_center[tid * 3 + 0] * nx
                      + plane_center[tid * 3 + 1] * ny
                      + plane_center[tid * 3 + 2] * nz;
        pl[256 + tid] = plane_min[tid * 3 + 0];
        pl[320 + tid] = plane_min[tid * 3 + 1];
        pl[384 + tid] = plane_min[tid * 3 + 2];
        pl[448 + tid] = plane_max[tid * 3 + 0];
        pl[512 + tid] = plane_max[tid * 3 + 1];
        pl[576 + tid] = plane_max[tid * 3 + 2];
    }
    if (tid < 3) ctr[tid] = centers[tid];
    __syncthreads();

    const float cx = ctr[0], cy = ctr[1], cz = ctr[2];

    // warp owns planes 4*wg..4*wg+3; lane owns dims 4*lane..4*lane+3 (f16 max)
    uint32_t poolv[4][2];
#pragma unroll
    for (int j = 0; j < 4; j++) { poolv[j][0] = 0u; poolv[j][1] = 0u; }

    for (int t = blockIdx.x; t < NT; t += GRID) {
        const int gbase = t * TILE;

        // ---- load 256-pt feature tile -> f16 A (swizzled)
        {
            const float4* src = (const float4*)(feature + (size_t)gbase * 128);
#pragma unroll
            for (int jj = 0; jj < 16; jj++) {
                const int idx = tid + jj * THREADS;      // 8192 float4
                const int pt  = idx >> 5, k4 = idx & 31;
                const float4 f = src[idx];
                const uint32_t a = swz(OFF_A, pt, k4 >> 1) + (uint32_t)((k4 & 1) * 8);
                *(uint2*)(smem + a) = make_uint2(pack_h2(f.x, f.y), pack_h2(f.z, f.w));
            }
        }

        // ---- masks (warp-private: warp writes & reads only its 4 planes)
#pragma unroll
        for (int h = 0; h < 8; h++) {
            const int pt = gbase + 32 * h + lane;
            const float px = xyz[(size_t)pt * 3 + 0] + cx;
            const float py = xyz[(size_t)pt * 3 + 1] + cy;
            const float pz = xyz[(size_t)pt * 3 + 2] + cz;
#pragma unroll
            for (int j = 0; j < 4; j++) {
                const int p = 4 * wg + j;
                const float d = fabsf(px * pl[p] + py * pl[64 + p] + pz * pl[128 + p]
                                      - pl[192 + p]);
                bool ok = d < 0.05f;
                float mn, mx;
                mn = pl[256 + p]; mx = pl[448 + p];
                ok = ok && ((px >= mn && px < mx) || (mx == 0.f));
                mn = pl[320 + p]; mx = pl[512 + p];
                ok = ok && ((py >= mn && py < mx) || (mx == 0.f));
                mn = pl[384 + p]; mx = pl[576 + p];
                ok = ok && ((pz >= mn && pz < mx) || (mx == 0.f));
                const unsigned bal = __ballot_sync(0xffffffffu, ok);
                if (lane == 0) pms[p * 8 + h] = bal;
            }
        }
        __syncthreads();   // bar1: A ready

        // ---- layer 1 ----
        float acc[2][8][4];
#pragma unroll
        for (int i = 0; i < 2; i++)
#pragma unroll
            for (int j = 0; j < 8; j++)
#pragma unroll
                for (int q = 0; q < 4; q++) acc[i][j][q] = 0.f;

        do_layer(sb + OFF_A, sb + OFF_W1, acc, r2, c2, lane);

        // ---- epilogue 1: +b1, relu, f16 into H1
#pragma unroll
        for (int i = 0; i < 2; i++)
#pragma unroll
            for (int h = 0; h < 2; h++) {
                const int row = 32 * r2 + 16 * i + 8 * h + g;
#pragma unroll
                for (int j = 0; j < 8; j++) {
                    const int col0 = 64 * c2 + 8 * j + 2 * tig;
                    const float2 bb = *(const float2*)&b1s[col0];
                    const float v0 = fmaxf(acc[i][j][2 * h + 0] + bb.x, 0.f);
                    const float v1 = fmaxf(acc[i][j][2 * h + 1] + bb.y, 0.f);
                    const uint32_t a = swz(OFF_H1, row, 8 * c2 + j) + (uint32_t)(4 * tig);
                    *(uint32_t*)(smem + a) = pack_h2(v0, v1);
                }
            }
        __syncthreads();   // bar2: H1 ready; all A-reads done

        // ---- layer 2 ----
#pragma unroll
        for (int i = 0; i < 2; i++)
#pragma unroll
            for (int j = 0; j < 8; j++)
#pragma unroll
                for (int q = 0; q < 4; q++) acc[i][j][q] = 0.f;

        do_layer(sb + OFF_H1, sb + OFF_W2, acc, r2, c2, lane);

        // ---- epilogue 2: +b2, relu, f16 into A region (H2)
#pragma unroll
        for (int i = 0; i < 2; i++)
#pragma unroll
            for (int h = 0; h < 2; h++) {
                const int row = 32 * r2 + 16 * i + 8 * h + g;
#pragma unroll
                for (int j = 0; j < 8; j++) {
                    const int col0 = 64 * c2 + 8 * j + 2 * tig;
                    const float2 bb = *(const float2*)&b2s[col0];
                    const float v0 = fmaxf(acc[i][j][2 * h + 0] + bb.x, 0.f);
                    const float v1 = fmaxf(acc[i][j][2 * h + 1] + bb.y, 0.f);
                    const uint32_t a = swz(OFF_A, row, 8 * c2 + j) + (uint32_t)(4 * tig);
                    *(uint32_t*)(smem + a) = pack_h2(v0, v1);
                }
            }
        __syncthreads();   // bar3: H2 ready

        // ---- pool: warp's 4 planes over 256 points, f16 max (exact on f16)
#pragma unroll
        for (int j = 0; j < 4; j++) {
            const int p = 4 * wg + j;
#pragma unroll
            for (int h = 0; h < 8; h++) {
                unsigned bits = pms[p * 8 + h];
                while (bits) {
                    const int i = __ffs(bits) - 1;
                    bits &= bits - 1;
                    const int pt = 32 * h + i;
                    const uint2 raw = *(const uint2*)
                        (smem + swz(OFF_A, pt, lane >> 1) + 8 * (lane & 1));
                    const __half2 a0 = *(const __half2*)&raw.x;
                    const __half2 a1 = *(const __half2*)&raw.y;
                    __half2 p0 = *(__half2*)&poolv[j][0];
                    __half2 p1 = *(__half2*)&poolv[j][1];
                    p0 = __hmax2(p0, a0);
                    p1 = __hmax2(p1, a1);
                    poolv[j][0] = *(uint32_t*)&p0;
                    poolv[j][1] = *(uint32_t*)&p1;
                }
            }
        }
        __syncthreads();   // bar4: pool done; next tile's STS may overwrite A
    }

    // ---- merge (nonneg float max == uint max on float bits)
    {
        unsigned* o32 = (unsigned*)out;
#pragma unroll
        for (int j = 0; j < 4; j++) {
            const int p = 4 * wg + j;
            const int bidx = p * 128 + lane * 4;
            const float2 v0 = __half22float2(*(const __half2*)&poolv[j][0]);
            const float2 v1 = __half22float2(*(const __half2*)&poolv[j][1]);
            atomicMax(&o32[bidx + 0], __float_as_uint(v0.x));
            atomicMax(&o32[bidx + 1], __float_as_uint(v0.y));
            atomicMax(&o32[bidx + 2], __float_as_uint(v1.x));
            atomicMax(&o32[bidx + 3], __float_as_uint(v1.y));
        }
    }
}

__global__ void zero_out_kernel(float* __restrict__ out, int n) {
    const int i = blockIdx.x * blockDim.x + threadIdx.x;
    if (i < n) out[i] = 0.f;
}

extern "C" void kernel_launch(void* const* d_in, const int* in_sizes, int n_in,
                              void* d_out, int out_size)
{
    const float* feature      = (const float*)d_in[0];
    const float* xyz          = (const float*)d_in[1];
    const float* centers      = (const float*)d_in[2];
    const float* plane_center = (const float*)d_in[3];
    const float* plane_normal = (const float*)d_in[4];
    const float* plane_min    = (const float*)d_in[5];
    const float* plane_max    = (const float*)d_in[6];
    const float* W1           = (const float*)d_in[7];
    const float* g1           = (const float*)d_in[8];
    const float* b1           = (const float*)d_in[9];
    const float* W2           = (const float*)d_in[10];
    const float* g2           = (const float*)d_in[11];
    const float* b2           = (const float*)d_in[12];
    float* out = (float*)d_out;

    cudaFuncSetAttribute(plane_refine_w64,
                         cudaFuncAttributeMaxDynamicSharedMemorySize, SMEM_BYTES);

    zero_out_kernel<<<(P * 128 + 255) / 256, 256>>>(out, P * 128);
    plane_refine_w64<<<GRID, THREADS, SMEM_BYTES>>>(
        feature, xyz, centers, plane_center, plane_normal, plane_min, plane_max,
        W1, g1, b1, W2, g2, b2, out);
}

// round 14
// speedup vs baseline: 1.1616x; 1.0536x over previous
#include <cuda_runtime.h>
#include <cuda_fp16.h>
#include <cstdint>

// ---------------------------------------------------------------------------
// Plane_refine on sm_100: 2-layer pointwise MLP via fp16 mma.sync (f32 accum)
// + masked max-pool. 296 CTAs x 512 thr, 2 CTAs/SM (=32 warps/SM, the first
// config not register-pinned at 16 warps). 64-pt tiles, warp tile m16 x n32
// (acc 16 regs -> 64 regs/thread). H1 f16 roundtrip, H2 f16 aliases A,
// f16 pool (exact), warp-private masks (4 planes/warp).
// ---------------------------------------------------------------------------

constexpr int N_PTS   = 131072;
constexpr int TILE    = 64;
constexpr int NT      = N_PTS / TILE;     // 2048
constexpr int GRID    = 296;              // 2 per SM
constexpr int THREADS = 512;
constexpr int P       = 64;

// smem. f16 rows: 128 f16 = 256 B, 16B-chunk XOR swizzle chunk' = chunk^(row&7).
constexpr int OFF_W1  = 0;          // 32 KB
constexpr int OFF_W2  = 32768;      // 32 KB
constexpr int OFF_A   = 65536;      // 16 KB (64 rows): feature f16, later H2 f16
constexpr int OFF_H1  = 81920;      // 16 KB (64 rows): H1 f16
constexpr int OFF_MISC = 98304;
constexpr int OFF_B1   = OFF_MISC + 0;      // f32[128]
constexpr int OFF_B2   = OFF_MISC + 512;    // f32[128]
constexpr int OFF_PL   = OFF_MISC + 1024;   // f32[640]
constexpr int OFF_CTR  = OFF_MISC + 3584;   // f32[4]
constexpr int OFF_PMS  = OFF_MISC + 3600;   // u32[64][2]
constexpr int SMEM_BYTES = OFF_MISC + 4640; // 102,944 B x2 = 205,888 <= SM cap

__device__ __forceinline__ uint32_t smem_u32(const void* p) {
    uint32_t a;
    asm("{ .reg .u64 t; cvta.to.shared.u64 t, %1; cvt.u32.u64 %0, t; }"
        : "=r"(a) : "l"(p));
    return a;
}

__device__ __forceinline__ uint32_t swz(uint32_t region, int row, int kc) {
    return region + (uint32_t)(row * 256) + (uint32_t)((kc ^ (row & 7)) << 4);
}

__device__ __forceinline__ uint32_t pack_h2(float a, float b) {
    __half2 h = __floats2half2_rn(a, b);
    return *(uint32_t*)&h;
}

#define LDSM_X4(r0, r1, r2, r3, a) \
    asm volatile("ldmatrix.sync.aligned.m8n8.x4.shared.b16 {%0,%1,%2,%3}, [%4];" \
                 : "=r"(r0), "=r"(r1), "=r"(r2), "=r"(r3) : "r"(a))
#define MMA16816(d, a0, a1, a2, a3, b0, b1) \
    asm volatile("mma.sync.aligned.m16n8k16.row.col.f32.f16.f16.f32 " \
                 "{%0,%1,%2,%3}, {%4,%5,%6,%7}, {%8,%9}, {%0,%1,%2,%3};" \
                 : "+f"((d)[0]), "+f"((d)[1]), "+f"((d)[2]), "+f"((d)[3]) \
                 : "r"(a0), "r"(a1), "r"(a2), "r"(a3), "r"(b0), "r"(b1))

// One m16 x n32 x k128 block (B via non-trans ldmatrix, verified mapping).
__device__ __forceinline__ void do_layer(uint32_t aB, uint32_t wB,
                                         float acc[4][4],
                                         int r2, int c2, int lane)
{
    const int arow  = 16 * r2 + (lane & 15);
    const int abit  = (lane >> 4) & 1;
    const int rs    = arow & 7;
    const uint32_t aoff = (uint32_t)(arow * 256);
    const int bn    = 32 * c2 + (lane & 7) + (((lane >> 4) & 1) << 3);
    const int bbit  = (lane >> 3) & 1;
    const int ns    = bn & 7;
    const uint32_t boff = (uint32_t)(bn * 256);

#pragma unroll
    for (int kk = 0; kk < 8; kk++) {
        const uint32_t kcA = (uint32_t)(((2 * kk + abit) ^ rs) << 4);
        const uint32_t kcB = (uint32_t)(((2 * kk + bbit) ^ ns) << 4);
        uint32_t a[4], b[8];
        LDSM_X4(a[0], a[1], a[2], a[3], aB + aoff + kcA);
        LDSM_X4(b[0], b[1], b[2], b[3], wB + boff + kcB);
        LDSM_X4(b[4], b[5], b[6], b[7], wB + boff + 4096 + kcB);
#pragma unroll
        for (int j = 0; j < 4; j++)
            MMA16816(acc[j], a[0], a[1], a[2], a[3], b[2 * j], b[2 * j + 1]);
    }
}

__global__ void __launch_bounds__(THREADS, 2)
plane_refine_o2(const float* __restrict__ feature, const float* __restrict__ xyz,
                const float* __restrict__ centers,
                const float* __restrict__ plane_center, const float* __restrict__ plane_normal,
                const float* __restrict__ plane_min, const float* __restrict__ plane_max,
                const float* __restrict__ W1, const float* __restrict__ g1,
                const float* __restrict__ b1,
                const float* __restrict__ W2, const float* __restrict__ g2,
                const float* __restrict__ b2,
                float* __restrict__ out)
{
    extern __shared__ char smem[];
    const uint32_t sb = smem_u32(smem);

    float*    b1s = (float*)(smem + OFF_B1);
    float*    b2s = (float*)(smem + OFF_B2);
    float*    pl  = (float*)(smem + OFF_PL);
    float*    ctr = (float*)(smem + OFF_CTR);
    unsigned* pms = (unsigned*)(smem + OFF_PMS);

    const int tid  = threadIdx.x;
    const int lane = tid & 31;
    const int wg   = tid >> 5;      // 0..15
    const int r2   = wg & 3;        // m-block: rows 16*r2
    const int c2   = wg >> 2;       // n-block: cols 32*c2
    const int g    = lane >> 2;
    const int tig  = lane & 3;

    // ---- prologue: weights (fold g, f16, swizzled), consts
    for (int idx = tid; idx < 16384; idx += THREADS) {
        const int o = idx >> 7, k = idx & 127;
        const uint32_t a1 = swz(0, o, k >> 3) + (uint32_t)((k & 7) * 2);
        *(__half*)(smem + a1 + OFF_W1) = __float2half_rn(W1[idx] * g1[o]);
        *(__half*)(smem + a1 + OFF_W2) = __float2half_rn(W2[idx] * g2[o]);
    }
    if (tid < 128) { b1s[tid] = b1[tid]; b2s[tid] = b2[tid]; }
    if (tid < P) {
        const float nx = plane_normal[tid * 3 + 0];
        const float ny = plane_normal[tid * 3 + 1];
        const float nz = plane_normal[tid * 3 + 2];
        pl[tid]       = nx;  pl[64 + tid]  = ny;  pl[128 + tid] = nz;
        pl[192 + tid] = plane_center[tid * 3 + 0] * nx
                      + plane_center[tid * 3 + 1] * ny
                      + plane_center[tid * 3 + 2] * nz;
        pl[256 + tid] = plane_min[tid * 3 + 0];
        pl[320 + tid] = plane_min[tid * 3 + 1];
        pl[384 + tid] = plane_min[tid * 3 + 2];
        pl[448 + tid] = plane_max[tid * 3 + 0];
        pl[512 + tid] = plane_max[tid * 3 + 1];
        pl[576 + tid] = plane_max[tid * 3 + 2];
    }
    if (tid < 3) ctr[tid] = centers[tid];
    __syncthreads();

    const float cx = ctr[0], cy = ctr[1], cz = ctr[2];

    // warp owns planes 4*wg..4*wg+3; lane owns dims 4*lane..4*lane+3 (f16 max)
    uint32_t poolv[4][2];
#pragma unroll
    for (int j = 0; j < 4; j++) { poolv[j][0] = 0u; poolv[j][1] = 0u; }

    for (int t = blockIdx.x; t < NT; t += GRID) {
        const int gbase = t * TILE;

        // ---- load 64-pt feature tile -> f16 A (swizzled)
        {
            const float4* src = (const float4*)(feature + (size_t)gbase * 128);
#pragma unroll
            for (int jj = 0; jj < 4; jj++) {
                const int idx = tid + jj * THREADS;      // 2048 float4
                const int pt  = idx >> 5, k4 = idx & 31;
                const float4 f = src[idx];
                const uint32_t a = swz(OFF_A, pt, k4 >> 1) + (uint32_t)((k4 & 1) * 8);
                *(uint2*)(smem + a) = make_uint2(pack_h2(f.x, f.y), pack_h2(f.z, f.w));
            }
        }

        // ---- masks (warp-private: warp writes & reads only its 4 planes)
#pragma unroll
        for (int h = 0; h < 2; h++) {
            const int pt = gbase + 32 * h + lane;
            const float px = xyz[(size_t)pt * 3 + 0] + cx;
            const float py = xyz[(size_t)pt * 3 + 1] + cy;
            const float pz = xyz[(size_t)pt * 3 + 2] + cz;
#pragma unroll
            for (int j = 0; j < 4; j++) {
                const int p = 4 * wg + j;
                const float d = fabsf(px * pl[p] + py * pl[64 + p] + pz * pl[128 + p]
                                      - pl[192 + p]);
                bool ok = d < 0.05f;
                float mn, mx;
                mn = pl[256 + p]; mx = pl[448 + p];
                ok = ok && ((px >= mn && px < mx) || (mx == 0.f));
                mn = pl[320 + p]; mx = pl[512 + p];
                ok = ok && ((py >= mn && py < mx) || (mx == 0.f));
                mn = pl[384 + p]; mx = pl[576 + p];
                ok = ok && ((pz >= mn && pz < mx) || (mx == 0.f));
                const unsigned bal = __ballot_sync(0xffffffffu, ok);
                if (lane == 0) pms[p * 2 + h] = bal;
            }
        }
        __syncthreads();   // bar1: A ready

        // ---- layer 1 ----
        float acc[4][4];
#pragma unroll
        for (int j = 0; j < 4; j++)
#pragma unroll
            for (int q = 0; q < 4; q++) acc[j][q] = 0.f;

        do_layer(sb + OFF_A, sb + OFF_W1, acc, r2, c2, lane);

        // ---- epilogue 1: +b1, relu, f16 into H1
#pragma unroll
        for (int h = 0; h < 2; h++) {
            const int row = 16 * r2 + 8 * h + g;
#pragma unroll
            for (int j = 0; j < 4; j++) {
                const int col0 = 32 * c2 + 8 * j + 2 * tig;
                const float2 bb = *(const float2*)&b1s[col0];
                const float v0 = fmaxf(acc[j][2 * h + 0] + bb.x, 0.f);
                const float v1 = fmaxf(acc[j][2 * h + 1] + bb.y, 0.f);
                const uint32_t a = swz(OFF_H1, row, 4 * c2 + j) + (uint32_t)(4 * tig);
                *(uint32_t*)(smem + a) = pack_h2(v0, v1);
            }
        }
        __syncthreads();   // bar2: H1 ready; all A-reads done

        // ---- layer 2 ----
#pragma unroll
        for (int j = 0; j < 4; j++)
#pragma unroll
            for (int q = 0; q < 4; q++) acc[j][q] = 0.f;

        do_layer(sb + OFF_H1, sb + OFF_W2, acc, r2, c2, lane);

        // ---- epilogue 2: +b2, relu, f16 into A region (H2)
#pragma unroll
        for (int h = 0; h < 2; h++) {
            const int row = 16 * r2 + 8 * h + g;
#pragma unroll
            for (int j = 0; j < 4; j++) {
                const int col0 = 32 * c2 + 8 * j + 2 * tig;
                const float2 bb = *(const float2*)&b2s[col0];
                const float v0 = fmaxf(acc[j][2 * h + 0] + bb.x, 0.f);
                const float v1 = fmaxf(acc[j][2 * h + 1] + bb.y, 0.f);
                const uint32_t a = swz(OFF_A, row, 4 * c2 + j) + (uint32_t)(4 * tig);
                *(uint32_t*)(smem + a) = pack_h2(v0, v1);
            }
        }
        __syncthreads();   // bar3: H2 ready

        // ---- pool: warp's 4 planes over 64 points, f16 max (exact on f16)
#pragma unroll
        for (int j = 0; j < 4; j++) {
            const int p = 4 * wg + j;
#pragma unroll
            for (int h = 0; h < 2; h++) {
                unsigned bits = pms[p * 2 + h];
                while (bits) {
                    const int i = __ffs(bits) - 1;
                    bits &= bits - 1;
                    const int pt = 32 * h + i;
                    const uint2 raw = *(const uint2*)
                        (smem + swz(OFF_A, pt, lane >> 1) + 8 * (lane & 1));
                    const __half2 a0 = *(const __half2*)&raw.x;
                    const __half2 a1 = *(const __half2*)&raw.y;
                    __half2 p0 = *(__half2*)&poolv[j][0];
                    __half2 p1 = *(__half2*)&poolv[j][1];
                    p0 = __hmax2(p0, a0);
                    p1 = __hmax2(p1, a1);
                    poolv[j][0] = *(uint32_t*)&p0;
                    poolv[j][1] = *(uint32_t*)&p1;
                }
            }
        }
        __syncthreads();   // bar4: pool done; next tile's STS may overwrite A
    }

    // ---- merge (nonneg float max == uint max on float bits)
    {
        unsigned* o32 = (unsigned*)out;
#pragma unroll
        for (int j = 0; j < 4; j++) {
            const int p = 4 * wg + j;
            const int bidx = p * 128 + lane * 4;
            const float2 v0 = __half22float2(*(const __half2*)&poolv[j][0]);
            const float2 v1 = __half22float2(*(const __half2*)&poolv[j][1]);
            atomicMax(&o32[bidx + 0], __float_as_uint(v0.x));
            atomicMax(&o32[bidx + 1], __float_as_uint(v0.y));
            atomicMax(&o32[bidx + 2], __float_as_uint(v1.x));
            atomicMax(&o32[bidx + 3], __float_as_uint(v1.y));
        }
    }
}

__global__ void zero_out_kernel(float* __restrict__ out, int n) {
    const int i = blockIdx.x * blockDim.x + threadIdx.x;
    if (i < n) out[i] = 0.f;
}

extern "C" void kernel_launch(void* const* d_in, const int* in_sizes, int n_in,
                              void* d_out, int out_size)
{
    const float* feature      = (const float*)d_in[0];
    const float* xyz          = (const float*)d_in[1];
    const float* centers      = (const float*)d_in[2];
    const float* plane_center = (const float*)d_in[3];
    const float* plane_normal = (const float*)d_in[4];
    const float* plane_min    = (const float*)d_in[5];
    const float* plane_max    = (const float*)d_in[6];
    const float* W1           = (const float*)d_in[7];
    const float* g1           = (const float*)d_in[8];
    const float* b1           = (const float*)d_in[9];
    const float* W2           = (const float*)d_in[10];
    const float* g2           = (const float*)d_in[11];
    const float* b2           = (const float*)d_in[12];
    float* out = (float*)d_out;

    cudaFuncSetAttribute(plane_refine_o2,
                         cudaFuncAttributeMaxDynamicSharedMemorySize, SMEM_BYTES);

    zero_out_kernel<<<(P * 128 + 255) / 256, 256>>>(out, P * 128);
    plane_refine_o2<<<GRID, THREADS, SMEM_BYTES>>>(
        feature, xyz, centers, plane_center, plane_normal, plane_min, plane_max,
        W1, g1, b1, W2, g2, b2, out);
}

// round 15
// speedup vs baseline: 1.2646x; 1.0887x over previous
#include <cuda_runtime.h>
#include <cuda_fp16.h>
#include <cstdint>

// ---------------------------------------------------------------------------
// Plane_refine on sm_100: 2-layer pointwise MLP via fp16 mma.sync (f32 accum)
// + masked max-pool. 296 CTAs x 512 thr, 2 CTAs/SM (32 warps/SM). 64-pt tiles,
// warp tile m16 x n32 (64 regs/thread). f16x2 epilogues (F2FP+HADD2+HMAX2),
// pre-packed half2 biases, hoisted mask coordinate loads. H1 f16 roundtrip,
// H2 f16 aliases A, f16 pool (exact), warp-private masks (4 planes/warp).
// ---------------------------------------------------------------------------

constexpr int N_PTS   = 131072;
constexpr int TILE    = 64;
constexpr int NT      = N_PTS / TILE;     // 2048
constexpr int GRID    = 296;              // 2 per SM
constexpr int THREADS = 512;
constexpr int P       = 64;

// smem. f16 rows: 128 f16 = 256 B, 16B-chunk XOR swizzle chunk' = chunk^(row&7).
constexpr int OFF_W1  = 0;          // 32 KB
constexpr int OFF_W2  = 32768;      // 32 KB
constexpr int OFF_A   = 65536;      // 16 KB (64 rows): feature f16, later H2 f16
constexpr int OFF_H1  = 81920;      // 16 KB (64 rows): H1 f16
constexpr int OFF_MISC = 98304;
constexpr int OFF_B1   = OFF_MISC + 0;      // half2[64] packed bias1 (256 B)
constexpr int OFF_B2   = OFF_MISC + 256;    // half2[64] packed bias2 (256 B)
constexpr int OFF_PL   = OFF_MISC + 1024;   // f32[640]
constexpr int OFF_CTR  = OFF_MISC + 3584;   // f32[4]
constexpr int OFF_PMS  = OFF_MISC + 3600;   // u32[64][2]
constexpr int SMEM_BYTES = OFF_MISC + 4640; // 102,944 B x2 = 205,888 <= SM cap

__device__ __forceinline__ uint32_t smem_u32(const void* p) {
    uint32_t a;
    asm("{ .reg .u64 t; cvta.to.shared.u64 t, %1; cvt.u32.u64 %0, t; }"
        : "=r"(a) : "l"(p));
    return a;
}

__device__ __forceinline__ uint32_t swz(uint32_t region, int row, int kc) {
    return region + (uint32_t)(row * 256) + (uint32_t)((kc ^ (row & 7)) << 4);
}

__device__ __forceinline__ uint32_t pack_h2(float a, float b) {
    __half2 h = __floats2half2_rn(a, b);   // a -> low 16 bits
    return *(uint32_t*)&h;
}

#define LDSM_X4(r0, r1, r2, r3, a) \
    asm volatile("ldmatrix.sync.aligned.m8n8.x4.shared.b16 {%0,%1,%2,%3}, [%4];" \
                 : "=r"(r0), "=r"(r1), "=r"(r2), "=r"(r3) : "r"(a))
#define MMA16816(d, a0, a1, a2, a3, b0, b1) \
    asm volatile("mma.sync.aligned.m16n8k16.row.col.f32.f16.f16.f32 " \
                 "{%0,%1,%2,%3}, {%4,%5,%6,%7}, {%8,%9}, {%0,%1,%2,%3};" \
                 : "+f"((d)[0]), "+f"((d)[1]), "+f"((d)[2]), "+f"((d)[3]) \
                 : "r"(a0), "r"(a1), "r"(a2), "r"(a3), "r"(b0), "r"(b1))

// One m16 x n32 x k128 block (B via non-trans ldmatrix, verified mapping).
__device__ __forceinline__ void do_layer(uint32_t aB, uint32_t wB,
                                         float acc[4][4],
                                         int r2, int c2, int lane)
{
    const int arow  = 16 * r2 + (lane & 15);
    const int abit  = (lane >> 4) & 1;
    const int rs    = arow & 7;
    const uint32_t aoff = (uint32_t)(arow * 256);
    const int bn    = 32 * c2 + (lane & 7) + (((lane >> 4) & 1) << 3);
    const int bbit  = (lane >> 3) & 1;
    const int ns    = bn & 7;
    const uint32_t boff = (uint32_t)(bn * 256);

#pragma unroll
    for (int kk = 0; kk < 8; kk++) {
        const uint32_t kcA = (uint32_t)(((2 * kk + abit) ^ rs) << 4);
        const uint32_t kcB = (uint32_t)(((2 * kk + bbit) ^ ns) << 4);
        uint32_t a[4], b[8];
        LDSM_X4(a[0], a[1], a[2], a[3], aB + aoff + kcA);
        LDSM_X4(b[0], b[1], b[2], b[3], wB + boff + kcB);
        LDSM_X4(b[4], b[5], b[6], b[7], wB + boff + 4096 + kcB);
#pragma unroll
        for (int j = 0; j < 4; j++)
            MMA16816(acc[j], a[0], a[1], a[2], a[3], b[2 * j], b[2 * j + 1]);
    }
}

__global__ void __launch_bounds__(THREADS, 2)
plane_refine_h2(const float* __restrict__ feature, const float* __restrict__ xyz,
                const float* __restrict__ centers,
                const float* __restrict__ plane_center, const float* __restrict__ plane_normal,
                const float* __restrict__ plane_min, const float* __restrict__ plane_max,
                const float* __restrict__ W1, const float* __restrict__ g1,
                const float* __restrict__ b1,
                const float* __restrict__ W2, const float* __restrict__ g2,
                const float* __restrict__ b2,
                float* __restrict__ out)
{
    extern __shared__ char smem[];
    const uint32_t sb = smem_u32(smem);

    __half2*  bh1 = (__half2*)(smem + OFF_B1);
    __half2*  bh2 = (__half2*)(smem + OFF_B2);
    float*    pl  = (float*)(smem + OFF_PL);
    float*    ctr = (float*)(smem + OFF_CTR);
    unsigned* pms = (unsigned*)(smem + OFF_PMS);

    const int tid  = threadIdx.x;
    const int lane = tid & 31;
    const int wg   = tid >> 5;      // 0..15
    const int r2   = wg & 3;        // m-block: rows 16*r2
    const int c2   = wg >> 2;       // n-block: cols 32*c2
    const int g    = lane >> 2;
    const int tig  = lane & 3;

    // ---- prologue: weights (fold g, f16, swizzled), packed biases, consts
    for (int idx = tid; idx < 16384; idx += THREADS) {
        const int o = idx >> 7, k = idx & 127;
        const uint32_t a1 = swz(0, o, k >> 3) + (uint32_t)((k & 7) * 2);
        *(__half*)(smem + a1 + OFF_W1) = __float2half_rn(W1[idx] * g1[o]);
        *(__half*)(smem + a1 + OFF_W2) = __float2half_rn(W2[idx] * g2[o]);
    }
    if (tid < 64) {
        bh1[tid] = __floats2half2_rn(b1[2 * tid], b1[2 * tid + 1]);
        bh2[tid] = __floats2half2_rn(b2[2 * tid], b2[2 * tid + 1]);
    }
    if (tid < P) {
        const float nx = plane_normal[tid * 3 + 0];
        const float ny = plane_normal[tid * 3 + 1];
        const float nz = plane_normal[tid * 3 + 2];
        pl[tid]       = nx;  pl[64 + tid]  = ny;  pl[128 + tid] = nz;
        pl[192 + tid] = plane_center[tid * 3 + 0] * nx
                      + plane_center[tid * 3 + 1] * ny
                      + plane_center[tid * 3 + 2] * nz;
        pl[256 + tid] = plane_min[tid * 3 + 0];
        pl[320 + tid] = plane_min[tid * 3 + 1];
        pl[384 + tid] = plane_min[tid * 3 + 2];
        pl[448 + tid] = plane_max[tid * 3 + 0];
        pl[512 + tid] = plane_max[tid * 3 + 1];
        pl[576 + tid] = plane_max[tid * 3 + 2];
    }
    if (tid < 3) ctr[tid] = centers[tid];
    __syncthreads();

    const float cx = ctr[0], cy = ctr[1], cz = ctr[2];
    const __half2 zero2 = __float2half2_rn(0.f);

    // warp owns planes 4*wg..4*wg+3; lane owns dims 4*lane..4*lane+3 (f16 max)
    uint32_t poolv[4][2];
#pragma unroll
    for (int j = 0; j < 4; j++) { poolv[j][0] = 0u; poolv[j][1] = 0u; }

    for (int t = blockIdx.x; t < NT; t += GRID) {
        const int gbase = t * TILE;

        // ---- load 64-pt feature tile -> f16 A (swizzled)
        {
            const float4* src = (const float4*)(feature + (size_t)gbase * 128);
#pragma unroll
            for (int jj = 0; jj < 4; jj++) {
                const int idx = tid + jj * THREADS;      // 2048 float4
                const int pt  = idx >> 5, k4 = idx & 31;
                const float4 f = src[idx];
                const uint32_t a = swz(OFF_A, pt, k4 >> 1) + (uint32_t)((k4 & 1) * 8);
                *(uint2*)(smem + a) = make_uint2(pack_h2(f.x, f.y), pack_h2(f.z, f.w));
            }
        }

        // ---- masks: hoist point coords for both 32-pt chunks, then planes
        {
            const int pt0 = gbase + lane;
            const int pt1 = gbase + 32 + lane;
            const float px0 = xyz[(size_t)pt0 * 3 + 0] + cx;
            const float py0 = xyz[(size_t)pt0 * 3 + 1] + cy;
            const float pz0 = xyz[(size_t)pt0 * 3 + 2] + cz;
            const float px1 = xyz[(size_t)pt1 * 3 + 0] + cx;
            const float py1 = xyz[(size_t)pt1 * 3 + 1] + cy;
            const float pz1 = xyz[(size_t)pt1 * 3 + 2] + cz;
#pragma unroll
            for (int j = 0; j < 4; j++) {
                const int p = 4 * wg + j;
                const float nx = pl[p], ny = pl[64 + p], nz = pl[128 + p];
                const float pd = pl[192 + p];
                const float mnx = pl[256 + p], mny = pl[320 + p], mnz = pl[384 + p];
                const float mxx = pl[448 + p], mxy = pl[512 + p], mxz = pl[576 + p];

                bool ok0 = fabsf(px0 * nx + py0 * ny + pz0 * nz - pd) < 0.05f;
                ok0 = ok0 && ((px0 >= mnx && px0 < mxx) || (mxx == 0.f));
                ok0 = ok0 && ((py0 >= mny && py0 < mxy) || (mxy == 0.f));
                ok0 = ok0 && ((pz0 >= mnz && pz0 < mxz) || (mxz == 0.f));
                bool ok1 = fabsf(px1 * nx + py1 * ny + pz1 * nz - pd) < 0.05f;
                ok1 = ok1 && ((px1 >= mnx && px1 < mxx) || (mxx == 0.f));
                ok1 = ok1 && ((py1 >= mny && py1 < mxy) || (mxy == 0.f));
                ok1 = ok1 && ((pz1 >= mnz && pz1 < mxz) || (mxz == 0.f));

                const unsigned bal0 = __ballot_sync(0xffffffffu, ok0);
                const unsigned bal1 = __ballot_sync(0xffffffffu, ok1);
                if (lane == 0) { pms[p * 2 + 0] = bal0; pms[p * 2 + 1] = bal1; }
            }
        }
        __syncthreads();   // bar1: A ready

        // ---- layer 1 ----
        float acc[4][4];
#pragma unroll
        for (int j = 0; j < 4; j++)
#pragma unroll
            for (int q = 0; q < 4; q++) acc[j][q] = 0.f;

        do_layer(sb + OFF_A, sb + OFF_W1, acc, r2, c2, lane);

        // ---- epilogue 1: f16x2 (cvt, +bias2, max0) into H1
#pragma unroll
        for (int h = 0; h < 2; h++) {
            const int row = 16 * r2 + 8 * h + g;
#pragma unroll
            for (int j = 0; j < 4; j++) {
                const __half2 bb = bh1[16 * c2 + 4 * j + tig];
                __half2 v = __floats2half2_rn(acc[j][2 * h + 0], acc[j][2 * h + 1]);
                v = __hmax2(__hadd2(v, bb), zero2);
                const uint32_t a = swz(OFF_H1, row, 4 * c2 + j) + (uint32_t)(4 * tig);
                *(uint32_t*)(smem + a) = *(uint32_t*)&v;
            }
        }
        __syncthreads();   // bar2: H1 ready; all A-reads done

        // ---- layer 2 ----
#pragma unroll
        for (int j = 0; j < 4; j++)
#pragma unroll
            for (int q = 0; q < 4; q++) acc[j][q] = 0.f;

        do_layer(sb + OFF_H1, sb + OFF_W2, acc, r2, c2, lane);

        // ---- epilogue 2: f16x2 into A region (H2)
#pragma unroll
        for (int h = 0; h < 2; h++) {
            const int row = 16 * r2 + 8 * h + g;
#pragma unroll
            for (int j = 0; j < 4; j++) {
                const __half2 bb = bh2[16 * c2 + 4 * j + tig];
                __half2 v = __floats2half2_rn(acc[j][2 * h + 0], acc[j][2 * h + 1]);
                v = __hmax2(__hadd2(v, bb), zero2);
                const uint32_t a = swz(OFF_A, row, 4 * c2 + j) + (uint32_t)(4 * tig);
                *(uint32_t*)(smem + a) = *(uint32_t*)&v;
            }
        }
        __syncthreads();   // bar3: H2 ready

        // ---- pool: warp's 4 planes over 64 points, f16 max (exact on f16)
#pragma unroll
        for (int j = 0; j < 4; j++) {
            const int p = 4 * wg + j;
#pragma unroll
            for (int h = 0; h < 2; h++) {
                unsigned bits = pms[p * 2 + h];
                while (bits) {
                    const int i = __ffs(bits) - 1;
                    bits &= bits - 1;
                    const int pt = 32 * h + i;
                    const uint2 raw = *(const uint2*)
                        (smem + swz(OFF_A, pt, lane >> 1) + 8 * (lane & 1));
                    const __half2 a0 = *(const __half2*)&raw.x;
                    const __half2 a1 = *(const __half2*)&raw.y;
                    __half2 p0 = *(__half2*)&poolv[j][0];
                    __half2 p1 = *(__half2*)&poolv[j][1];
                    p0 = __hmax2(p0, a0);
                    p1 = __hmax2(p1, a1);
                    poolv[j][0] = *(uint32_t*)&p0;
                    poolv[j][1] = *(uint32_t*)&p1;
                }
            }
        }
        __syncthreads();   // bar4: pool done; next tile's STS may overwrite A
    }

    // ---- merge (nonneg float max == uint max on float bits)
    {
        unsigned* o32 = (unsigned*)out;
#pragma unroll
        for (int j = 0; j < 4; j++) {
            const int p = 4 * wg + j;
            const int bidx = p * 128 + lane * 4;
            const float2 v0 = __half22float2(*(const __half2*)&poolv[j][0]);
            const float2 v1 = __half22float2(*(const __half2*)&poolv[j][1]);
            atomicMax(&o32[bidx + 0], __float_as_uint(v0.x));
            atomicMax(&o32[bidx + 1], __float_as_uint(v0.y));
            atomicMax(&o32[bidx + 2], __float_as_uint(v1.x));
            atomicMax(&o32[bidx + 3], __float_as_uint(v1.y));
        }
    }
}

__global__ void zero_out_kernel(float* __restrict__ out, int n) {
    const int i = blockIdx.x * blockDim.x + threadIdx.x;
    if (i < n) out[i] = 0.f;
}

extern "C" void kernel_launch(void* const* d_in, const int* in_sizes, int n_in,
                              void* d_out, int out_size)
{
    const float* feature      = (const float*)d_in[0];
    const float* xyz          = (const float*)d_in[1];
    const float* centers      = (const float*)d_in[2];
    const float* plane_center = (const float*)d_in[3];
    const float* plane_normal = (const float*)d_in[4];
    const float* plane_min    = (const float*)d_in[5];
    const float* plane_max    = (const float*)d_in[6];
    const float* W1           = (const float*)d_in[7];
    const float* g1           = (const float*)d_in[8];
    const float* b1           = (const float*)d_in[9];
    const float* W2           = (const float*)d_in[10];
    const float* g2           = (const float*)d_in[11];
    const float* b2           = (const float*)d_in[12];
    float* out = (float*)d_out;

    cudaFuncSetAttribute(plane_refine_h2,
                         cudaFuncAttributeMaxDynamicSharedMemorySize, SMEM_BYTES);

    zero_out_kernel<<<(P * 128 + 255) / 256, 256>>>(out, P * 128);
    plane_refine_h2<<<GRID, THREADS, SMEM_BYTES>>>(
        feature, xyz, centers, plane_center, plane_normal, plane_min, plane_max,
        W1, g1, b1, W2, g2, b2, out);
}